// round 1
// baseline (speedup 1.0000x reference)
#include <cuda_runtime.h>

// ---------------------------------------------------------------------------
// SSIM (16,3,512,512) fp32, 11x11 gaussian window (sigma=1.5), zero padding.
// Strategy: separable conv, horizontal pass -> register ring of 11 rows x 5
// quantities -> vertical pass, all gaussian weights as compile-time
// immediates (FFMA-imm rt1 on sm_103a). Block = 128 threads = 128 columns.
// Grid = 48 planes x 4 col-strips x 4 row-bands = 768 blocks.
// ---------------------------------------------------------------------------

#define IMG_H 512
#define IMG_W 512
#define N_PLANES 48
#define TOTAL_PIX 12582912.0   // 16*3*512*512

// gaussian(11, sigma=1.5), normalized; offsets -5..5
__device__ __constant__ const float kDummy = 0.f; // (unused; keep no cbank deps)

#define GW0 0.26601172f
#define GW1 0.21300554f
#define GW2 0.10936069f
#define GW3 0.03600077f
#define GW4 0.00759876f
#define GW5 0.00102842f

__device__ double g_acc;

__global__ void zero_kernel() { g_acc = 0.0; }

__global__ void final_kernel(float* __restrict__ out) {
    out[0] = (float)(g_acc / TOTAL_PIX);
}

__global__ __launch_bounds__(128)
void ssim_kernel(const float* __restrict__ img1, const float* __restrict__ img2) {
    // weights indexable at compile time (unrolled loops -> immediates)
    const float GW[11] = {GW5, GW4, GW3, GW2, GW1, GW0, GW1, GW2, GW3, GW4, GW5};

    const int plane = blockIdx.x;     // 0..47
    const int strip = blockIdx.y;     // 0..3  (column strips of 128)
    const int band  = blockIdx.z;     // 0..3  (row bands of 128)
    const int tx    = threadIdx.x;    // 0..127

    const int col0 = strip * 128;
    const int row0 = band * 128;

    const float* __restrict__ p1 = img1 + (size_t)plane * (IMG_H * IMG_W);
    const float* __restrict__ p2 = img2 + (size_t)plane * (IMG_H * IMG_W);

    __shared__ float sa[144];
    __shared__ float sb[144];

    // ring[k][q]: horizontal sums of input row r stored at slot k=(r+5)%11
    float ring[11][5];
#pragma unroll
    for (int k = 0; k < 11; ++k)
#pragma unroll
        for (int q = 0; q < 5; ++q) ring[k][q] = 0.f;

    float acc = 0.f;

    const float C1 = 1e-4f;
    const float C2 = 9e-4f;
    const float C2E = 9e-4f + 1e-6f;

    // iterate input rows y_in = row0-5 + n, n = t*11+k, emit output y = y_in-5
    for (int t = 0; t < 13; ++t) {
#pragma unroll
        for (int k = 0; k < 11; ++k) {
            const int n = t * 11 + k;
            const int y_in = row0 - 5 + n;

            __syncthreads();
            {
                const bool rowok = ((unsigned)y_in < (unsigned)IMG_H);
                const int c0 = col0 - 5 + tx;
                const float* r1 = p1 + y_in * IMG_W;
                const float* r2 = p2 + y_in * IMG_W;
                const bool ok0 = rowok && ((unsigned)c0 < (unsigned)IMG_W);
                sa[tx] = ok0 ? r1[c0] : 0.f;
                sb[tx] = ok0 ? r2[c0] : 0.f;
                if (tx < 10) {
                    const int c1 = c0 + 128;
                    const bool ok1 = rowok && ((unsigned)c1 < (unsigned)IMG_W);
                    sa[128 + tx] = ok1 ? r1[c1] : 0.f;
                    sb[128 + tx] = ok1 ? r2[c1] : 0.f;
                }
            }
            __syncthreads();

            // horizontal pass for this row, 5 quantities
            float h0 = 0.f, h1 = 0.f, h2 = 0.f, h3 = 0.f, h4 = 0.f;
#pragma unroll
            for (int i = 0; i < 11; ++i) {
                const float w = GW[i];
                const float a = sa[tx + i];
                const float b = sb[tx + i];
                const float pa = w * a;          // imm mul
                const float qb = w * b;          // imm mul
                h0 = fmaf(w, a, h0);             // imm fma
                h1 = fmaf(w, b, h1);             // imm fma
                h2 = fmaf(pa, a, h2);            // w*a*a
                h3 = fmaf(qb, b, h3);            // w*b*b
                h4 = fmaf(pa, b, h4);            // w*a*b
            }
            ring[k][0] = h0; ring[k][1] = h1; ring[k][2] = h2;
            ring[k][3] = h3; ring[k][4] = h4;

            // vertical pass + SSIM pointwise once ring holds rows y-5..y+5
            if (n >= 10 && n < 138) {
                float m1 = 0.f, m2 = 0.f, s11 = 0.f, s22 = 0.f, s12 = 0.f;
#pragma unroll
                for (int j = 0; j < 11; ++j) {
                    const int s = (k + 1 + j) % 11;   // static in unrolled ctx
                    const float w = GW[j];
                    m1  = fmaf(w, ring[s][0], m1);
                    m2  = fmaf(w, ring[s][1], m2);
                    s11 = fmaf(w, ring[s][2], s11);
                    s22 = fmaf(w, ring[s][3], s22);
                    s12 = fmaf(w, ring[s][4], s12);
                }
                const float mu1sq = m1 * m1;
                const float mu2sq = m2 * m2;
                const float mu12  = m1 * m2;
                const float sig1  = s11 - mu1sq;
                const float sig2  = s22 - mu2sq;
                const float sig12 = s12 - mu12;
                const float v1  = 2.f * sig12 + C2;
                const float v2  = sig1 + sig2 + C2E;
                const float num = fmaf(2.f, mu12, C1) * v1;
                const float den = (mu1sq + mu2sq + C1) * v2;
                acc += num / den;
            }
        }
    }

    // block reduction -> one double atomic per block
#pragma unroll
    for (int o = 16; o > 0; o >>= 1)
        acc += __shfl_xor_sync(0xFFFFFFFFu, acc, o);

    __shared__ float wsum[4];
    if ((tx & 31) == 0) wsum[tx >> 5] = acc;
    __syncthreads();
    if (tx == 0) {
        const float s = wsum[0] + wsum[1] + wsum[2] + wsum[3];
        atomicAdd(&g_acc, (double)s);
    }
}

extern "C" void kernel_launch(void* const* d_in, const int* in_sizes, int n_in,
                              void* d_out, int out_size) {
    const float* img1 = (const float*)d_in[0];
    const float* img2 = (const float*)d_in[1];
    float* out = (float*)d_out;
    (void)in_sizes; (void)n_in; (void)out_size;

    zero_kernel<<<1, 1>>>();
    dim3 grid(N_PLANES, 4, 4);
    ssim_kernel<<<grid, 128>>>(img1, img2);
    final_kernel<<<1, 1>>>(out);
}

// round 2
// speedup vs baseline: 1.4842x; 1.4842x over previous
#include <cuda_runtime.h>

// ---------------------------------------------------------------------------
// SSIM (16,3,512,512) fp32, 11x11 gaussian (sigma=1.5), zero padding.
// Separable conv; horizontal pass -> register ring (11 rows x 5 quantities)
// -> vertical pass with compile-time-immediate weights (FFMA-imm rt1).
// Round-2 changes:
//   * 11 rows loaded per __syncthreads pair (MLP ~25, 26 syncs vs 286)
//   * single kernel: last block finalizes mean and resets accumulators
//   * __fdividef in epilogue
// Block = 128 threads = 128 columns; grid = 48 planes x 4 strips x 4 bands.
// ---------------------------------------------------------------------------

#define IMG_H 512
#define IMG_W 512
#define N_PLANES 48
#define N_BLOCKS (48 * 4 * 4)
#define TOTAL_PIX 12582912.0   // 16*3*512*512

#define GW0 0.26601172f
#define GW1 0.21300554f
#define GW2 0.10936069f
#define GW3 0.03600077f
#define GW4 0.00759876f
#define GW5 0.00102842f

__device__ double g_acc;            // zero-initialized at module load
__device__ unsigned int g_count;    // zero-initialized at module load

__global__ __launch_bounds__(128)
void ssim_kernel(const float* __restrict__ img1, const float* __restrict__ img2,
                 float* __restrict__ out) {
    const float GW[11] = {GW5, GW4, GW3, GW2, GW1, GW0, GW1, GW2, GW3, GW4, GW5};

    const int plane = blockIdx.x;     // 0..47
    const int strip = blockIdx.y;     // 0..3
    const int band  = blockIdx.z;     // 0..3
    const int tx    = threadIdx.x;    // 0..127

    const int col0 = strip * 128;
    const int row0 = band * 128;

    const float* __restrict__ p1 = img1 + (size_t)plane * (IMG_H * IMG_W);
    const float* __restrict__ p2 = img2 + (size_t)plane * (IMG_H * IMG_W);

    __shared__ float sa[11][144];
    __shared__ float sb[11][144];

    float ring[11][5];
#pragma unroll
    for (int k = 0; k < 11; ++k)
#pragma unroll
        for (int q = 0; q < 5; ++q) ring[k][q] = 0.f;

    float acc = 0.f;

    const float C1  = 1e-4f;
    const float C2  = 9e-4f;
    const float C2E = 9e-4f + 1e-6f;

    const int c0  = col0 - 5 + tx;
    const bool colok0 = ((unsigned)c0 < (unsigned)IMG_W);
    const int c1  = c0 + 128;
    const bool colok1 = (tx < 10) && ((unsigned)c1 < (unsigned)IMG_W);

    // input rows y = row0 - 5 + n, n = t*11 + k; output emitted for n in [10,138)
    for (int t = 0; t < 13; ++t) {
        const int base = row0 - 5 + t * 11;

        __syncthreads();   // previous chunk's smem fully consumed
#pragma unroll
        for (int r = 0; r < 11; ++r) {
            const int y = base + r;
            const bool rowok = ((unsigned)y < (unsigned)IMG_H);
            const float* r1 = p1 + y * IMG_W;
            const float* r2 = p2 + y * IMG_W;
            const bool ok0 = rowok && colok0;
            sa[r][tx] = ok0 ? __ldg(r1 + c0) : 0.f;
            sb[r][tx] = ok0 ? __ldg(r2 + c0) : 0.f;
            if (tx < 10) {
                const bool ok1 = rowok && colok1;
                sa[r][128 + tx] = ok1 ? __ldg(r1 + c1) : 0.f;
                sb[r][128 + tx] = ok1 ? __ldg(r2 + c1) : 0.f;
            }
        }
        __syncthreads();   // chunk visible to all

#pragma unroll
        for (int k = 0; k < 11; ++k) {
            // horizontal pass: 5 quantities for input row n = t*11+k
            float h0 = 0.f, h1 = 0.f, h2 = 0.f, h3 = 0.f, h4 = 0.f;
#pragma unroll
            for (int i = 0; i < 11; ++i) {
                const float w = GW[i];
                const float a = sa[k][tx + i];
                const float b = sb[k][tx + i];
                const float pa = w * a;
                const float qb = w * b;
                h0 = fmaf(w, a, h0);
                h1 = fmaf(w, b, h1);
                h2 = fmaf(pa, a, h2);
                h3 = fmaf(qb, b, h3);
                h4 = fmaf(pa, b, h4);
            }
            ring[k][0] = h0; ring[k][1] = h1; ring[k][2] = h2;
            ring[k][3] = h3; ring[k][4] = h4;

            const int n = t * 11 + k;
            if (n >= 10 && n < 138) {
                float m1 = 0.f, m2 = 0.f, s11 = 0.f, s22 = 0.f, s12 = 0.f;
#pragma unroll
                for (int j = 0; j < 11; ++j) {
                    const int s = (k + 1 + j) % 11;   // static after unroll
                    const float w = GW[j];
                    m1  = fmaf(w, ring[s][0], m1);
                    m2  = fmaf(w, ring[s][1], m2);
                    s11 = fmaf(w, ring[s][2], s11);
                    s22 = fmaf(w, ring[s][3], s22);
                    s12 = fmaf(w, ring[s][4], s12);
                }
                const float mu1sq = m1 * m1;
                const float mu2sq = m2 * m2;
                const float mu12  = m1 * m2;
                const float sig1  = s11 - mu1sq;
                const float sig2  = s22 - mu2sq;
                const float sig12 = s12 - mu12;
                const float v1  = 2.f * sig12 + C2;
                const float v2  = sig1 + sig2 + C2E;
                const float num = fmaf(2.f, mu12, C1) * v1;
                const float den = (mu1sq + mu2sq + C1) * v2;
                acc += __fdividef(num, den);
            }
        }
    }

    // block reduction
#pragma unroll
    for (int o = 16; o > 0; o >>= 1)
        acc += __shfl_xor_sync(0xFFFFFFFFu, acc, o);

    __shared__ float wsum[4];
    if ((tx & 31) == 0) wsum[tx >> 5] = acc;
    __syncthreads();

    if (tx == 0) {
        const float s = wsum[0] + wsum[1] + wsum[2] + wsum[3];
        atomicAdd(&g_acc, (double)s);
        __threadfence();
        const unsigned int done = atomicAdd(&g_count, 1u);
        if (done == (unsigned)(N_BLOCKS - 1)) {
            // last block: finalize and reset for next graph replay
            const double total = atomicAdd(&g_acc, 0.0);
            out[0] = (float)(total / TOTAL_PIX);
            g_acc = 0.0;
            g_count = 0u;
            __threadfence();
        }
    }
}

extern "C" void kernel_launch(void* const* d_in, const int* in_sizes, int n_in,
                              void* d_out, int out_size) {
    const float* img1 = (const float*)d_in[0];
    const float* img2 = (const float*)d_in[1];
    float* out = (float*)d_out;
    (void)in_sizes; (void)n_in; (void)out_size;

    dim3 grid(N_PLANES, 4, 4);
    ssim_kernel<<<grid, 128>>>(img1, img2, out);
}